// round 2
// baseline (speedup 1.0000x reference)
#include <cuda_runtime.h>
#include <math.h>

#define H 256
#define W 256
#define V 192
#define D 256
#define S 256
#define HW (H*W)

// ---- geometry constants (double-derived, cast to f32) ----
#define SQRT2_D 3.141592653589793  /* placeholder guard against typo; real below */
#undef SQRT2_D
#define SQRT2_D 1.4142135623730951
#define DPf     ((float)(2.0 * SQRT2_D * 128.0 / 255.0))   /* sample spacing, 128-scaled px */
#define OFFf    ((float)(-SQRT2_D * 128.0))
#define INV_DPf ((float)(255.0 / (256.0 * SQRT2_D)))
#define DTf     ((float)(2.0 * SQRT2_D / 256.0))
#define PI_D    3.141592653589793

__device__ float2 g_img2[HW];      // (imgA, imgB) interleaved
__device__ float2 g_temp[V * D];   // residual sinogram, (A,B) interleaved

// ---------------------------------------------------------------------------
// interleave the two images so every bilinear corner is one LDG.64
// ---------------------------------------------------------------------------
__global__ void prep_kernel(const float* __restrict__ img) {
    int p = blockIdx.x * blockDim.x + threadIdx.x;
    g_img2[p] = make_float2(img[p], img[p + HW]);
}

__device__ __forceinline__ void slab(float A, float dir, float b0, float b1,
                                     float& lo, float& hi, bool& empty) {
    if (fabsf(dir) > 1e-7f) {
        float r = 1.0f / dir;
        float t1 = (b0 - A) * r, t2 = (b1 - A) * r;
        lo = fmaxf(lo, fminf(t1, t2));
        hi = fminf(hi, fmaxf(t1, t2));
    } else if (A < b0 || A > b1) {
        empty = true;
    }
}

// ---------------------------------------------------------------------------
// forward projection: one warp per (v,d) ray, lanes stride over samples.
// Interior t-range (all 4 corners provably valid) runs with zero bounds checks.
// ---------------------------------------------------------------------------
__global__ void __launch_bounds__(256) fwd_kernel(const float* __restrict__ proj) {
    const int warp = (blockIdx.x * blockDim.x + threadIdx.x) >> 5;
    const int lane = threadIdx.x & 31;
    const int v = warp >> 8;
    const int d = warp & 255;

    float cv, sv;
    {
        float af = (float)((double)v * (PI_D / 192.0));
        sincosf(af, &sv, &cv);
    }
    const float s128 = fmaf((float)d, DPf, OFFf);
    const float ax = fmaf(-s128, sv, 127.5f);   // xp = ax + t128*cv
    const float ay = fmaf( s128, cv, 127.5f);   // yp = ay + t128*sv

    float lo = -1e30f, hi = 1e30f;              // any-corner-valid superset
    float li = -1e30f, hii = 1e30f;             // all-corners-valid (interior) subset
    bool empty = false, iempty = false;
    slab(ax, cv, -1.001f, 256.001f, lo, hi, empty);
    slab(ay, sv, -1.001f, 256.001f, lo, hi, empty);
    slab(ax, cv, 0.001f, 254.999f, li, hii, iempty);
    slab(ay, sv, 0.001f, 254.999f, li, hii, iempty);

    float sA = 0.f, sB = 0.f;
    if (!empty) {
        int kLo = max(0,     (int)ceilf ((lo  - OFFf) * INV_DPf - 0.001f));
        int kHi = min(S - 1, (int)floorf((hi  - OFFf) * INV_DPf + 0.001f));
        int kiLo, kiHi;
        if (iempty || li > hii) { kiLo = 1; kiHi = 0; }
        else {
            kiLo = (int)ceilf ((li  - OFFf) * INV_DPf + 0.001f);
            kiHi = (int)floorf((hii - OFFf) * INV_DPf - 0.001f);
        }
        for (int k = kLo + lane; k <= kHi; k += 32) {
            float t128 = fmaf((float)k, DPf, OFFf);
            float xp = fmaf(t128, cv, ax);
            float yp = fmaf(t128, sv, ay);
            float x0f = floorf(xp), y0f = floorf(yp);
            float fx = xp - x0f, fy = yp - y0f;
            int ix0 = (int)x0f, iy0 = (int)y0f;
            int base = iy0 * W + ix0;
            float2 p00, p10, p01, p11;
            if (k >= kiLo && k <= kiHi) {           // interior: no checks
                p00 = g_img2[base];         p10 = g_img2[base + 1];
                p01 = g_img2[base + W];     p11 = g_img2[base + W + 1];
            } else {                                 // boundary: predicated loads
                p00 = p10 = p01 = p11 = make_float2(0.f, 0.f);
                bool vx0 = (unsigned)ix0       < (unsigned)W;
                bool vx1 = (unsigned)(ix0 + 1) < (unsigned)W;
                bool vy0 = (unsigned)iy0       < (unsigned)H;
                bool vy1 = (unsigned)(iy0 + 1) < (unsigned)H;
                if (vx0 && vy0) p00 = g_img2[base];
                if (vx1 && vy0) p10 = g_img2[base + 1];
                if (vx0 && vy1) p01 = g_img2[base + W];
                if (vx1 && vy1) p11 = g_img2[base + W + 1];
            }
            float gx = 1.f - fx, gy = 1.f - fy;
            float w00 = gx * gy, w10 = fx * gy, w01 = gx * fy, w11 = fx * fy;
            sA = fmaf(p00.x, w00, fmaf(p10.x, w10, fmaf(p01.x, w01, fmaf(p11.x, w11, sA))));
            sB = fmaf(p00.y, w00, fmaf(p10.y, w10, fmaf(p01.y, w01, fmaf(p11.y, w11, sB))));
        }
    }
    #pragma unroll
    for (int o = 16; o; o >>= 1) {
        sA += __shfl_xor_sync(0xffffffffu, sA, o);
        sB += __shfl_xor_sync(0xffffffffu, sB, o);
    }
    if (lane == 0) {
        g_temp[warp] = make_float2(fmaf(DTf, sA, -__ldg(proj + warp)),
                                   fmaf(DTf, sB, -__ldg(proj + V * D + warp)));
    }
}

// ---------------------------------------------------------------------------
// backprojection (exact adjoint, gather) fused with the SIRT-style update.
// Fractional-index formulation:
//   dx_{ab} = (fj-a)*svDP + (b-fk)*cvDP ,  dy_{ab} = (a-fj)*cvDP + (b-fk)*svDP
// hat(x) = __saturatef(1-|x|)  → single FADD.SAT.
// No bounds checks: interior pixels always have j0 in [0,254].
// ---------------------------------------------------------------------------
__global__ void __launch_bounds__(256) bwd_kernel(const float* __restrict__ img,
                                                  const float* __restrict__ wptr,
                                                  float* __restrict__ out) {
    __shared__ float4 sg[V];   // {svDP, cvDP, svI, cvI}
    const int tid = threadIdx.x;
    if (tid < V) {
        float af = (float)((double)tid * (PI_D / 192.0));
        float cv, sv;
        sincosf(af, &sv, &cv);
        sg[tid] = make_float4(sv * DPf, cv * DPf, sv * INV_DPf, cv * INV_DPf);
    }
    __syncthreads();

    const int p = blockIdx.x * blockDim.x + tid;
    const int ix = p & (W - 1);
    const int iy = p >> 8;
    const float px = (float)ix - 127.5f;
    const float py = (float)iy - 127.5f;
    const float npx = -px;

    float accA = 0.f, accB = 0.f;
    const float2* __restrict__ row = g_temp;

    #pragma unroll 4
    for (int v = 0; v < V; ++v, row += D) {
        const float4 q = sg[v];
        const float svDP = q.x, cvDP = q.y, svI = q.z, cvI = q.w;

        const float jc = fmaf(py, cvI, fmaf(npx, svI, 127.5f));  // detector index (frac)
        const float kc = fmaf(px, cvI, fmaf(py,  svI, 127.5f));  // ray-param index (frac)
        const float jf = floorf(jc), kf = floorf(kc);
        const float fj = jc - jf,    fk = kc - kf;
        const int   j0 = (int)jf;

        const float dx00 = fmaf(fj, svDP, -(fk * cvDP));
        const float u    = fmaf(fj, cvDP,  (fk * svDP));   // |dy00| = |u|
        const float dx10 = dx00 - svDP;
        const float dx01 = dx00 + cvDP;
        const float dx11 = dx10 + cvDP;
        const float e10  = u - cvDP;       // |dy10|
        const float e01  = u - svDP;       // |dy01|
        const float e11  = e10 - svDP;     // |dy11|

        const float hx00 = __saturatef(1.f - fabsf(dx00));
        const float hx10 = __saturatef(1.f - fabsf(dx10));
        const float hx01 = __saturatef(1.f - fabsf(dx01));
        const float hx11 = __saturatef(1.f - fabsf(dx11));
        const float hy00 = __saturatef(1.f - fabsf(u));
        const float hy10 = __saturatef(1.f - fabsf(e10));
        const float hy01 = __saturatef(1.f - fabsf(e01));
        const float hy11 = __saturatef(1.f - fabsf(e11));

        const float q0 = fmaf(hx01, hy01, hx00 * hy00);   // det j0   (sum over both k)
        const float q1 = fmaf(hx11, hy11, hx10 * hy10);   // det j0+1

        const float2 t0 = __ldg(row + j0);
        const float2 t1 = __ldg(row + j0 + 1);
        accA = fmaf(t0.x, q0, fmaf(t1.x, q1, accA));
        accB = fmaf(t0.y, q0, fmaf(t1.y, q1, accB));
    }

    const float wdt = __ldg(wptr) * DTf;
    out[p]      = fmaf(-wdt, accA, img[p]);
    out[p + HW] = fmaf(-wdt, accB, img[p + HW]);
}

// ---------------------------------------------------------------------------
extern "C" void kernel_launch(void* const* d_in, const int* in_sizes, int n_in,
                              void* d_out, int out_size) {
    const float* img  = (const float*)d_in[0];   // [2,1,256,256]
    const float* proj = (const float*)d_in[1];   // [2,1,192,256]
    const float* wptr = (const float*)d_in[2];   // [1]
    float* out = (float*)d_out;                  // [2,1,256,256]

    prep_kernel<<<HW / 256, 256>>>(img);
    fwd_kernel<<<(V * D * 32) / 256, 256>>>(proj);
    bwd_kernel<<<HW / 256, 256>>>(img, wptr, out);
}

// round 3
// speedup vs baseline: 1.3288x; 1.3288x over previous
#include <cuda_runtime.h>
#include <math.h>

#define H 256
#define W 256
#define V 192
#define D 256
#define S 256
#define HW (H*W)

#define SQRT2_D 1.4142135623730951
#define DPf     ((float)(2.0 * SQRT2_D * 128.0 / 255.0))   /* sample spacing, 128-scaled px */
#define OFFf    ((float)(-SQRT2_D * 128.0))
#define INV_DPf ((float)(255.0 / (256.0 * SQRT2_D)))
#define DTf     ((float)(2.0 * SQRT2_D / 256.0))
#define PI_D    3.141592653589793

__device__ float2 g_img2[HW];      // (imgA, imgB) interleaved
__device__ float2 g_temp[V * D];   // residual sinogram, (A,B) interleaved
__device__ float4 g_trig4[V];      // {svDP, cvDP, svI, cvI}, written by fwd

// ---------------------------------------------------------------------------
// interleave the two images: every bilinear corner becomes one LDG.64
// ---------------------------------------------------------------------------
__global__ void prep_kernel(const float* __restrict__ img) {
    int p = blockIdx.x * blockDim.x + threadIdx.x;           // 0 .. HW/2-1
    float2 a = ((const float2*)img)[p];
    float2 b = ((const float2*)(img + HW))[p];
    ((float4*)g_img2)[p] = make_float4(a.x, b.x, a.y, b.y);
}

__device__ __forceinline__ void slab(float A, float dir, float b0, float b1,
                                     float& lo, float& hi, bool& empty) {
    if (fabsf(dir) > 1e-7f) {
        float r = 1.0f / dir;
        float t1 = (b0 - A) * r, t2 = (b1 - A) * r;
        lo = fmaxf(lo, fminf(t1, t2));
        hi = fminf(hi, fmaxf(t1, t2));
    } else if (A < b0 || A > b1) {
        empty = true;
    }
}

__device__ __forceinline__ void accum4(float2 p00, float2 p10, float2 p01, float2 p11,
                                       float fx, float fy, float& sA, float& sB) {
    float gx = 1.f - fx, gy = 1.f - fy;
    float w00 = gx * gy, w10 = fx * gy, w01 = gx * fy, w11 = fx * fy;
    sA = fmaf(p00.x, w00, fmaf(p10.x, w10, fmaf(p01.x, w01, fmaf(p11.x, w11, sA))));
    sB = fmaf(p00.y, w00, fmaf(p10.y, w10, fmaf(p01.y, w01, fmaf(p11.y, w11, sB))));
}

// ---------------------------------------------------------------------------
// forward projection: one warp per (v,d) ray, lanes stride over samples.
// 3-loop split: boundary | interior (no checks, no branches) | boundary.
// All loop bounds are warp-uniform (one ray per warp).
// ---------------------------------------------------------------------------
__global__ void __launch_bounds__(256) fwd_kernel(const float* __restrict__ proj) {
    const int warp = (blockIdx.x * blockDim.x + threadIdx.x) >> 5;
    const int lane = threadIdx.x & 31;
    const int v = warp >> 8;
    const int d = warp & 255;

    float cv, sv;
    {
        float af = (float)((double)v * (PI_D / 192.0));
        sincosf(af, &sv, &cv);
    }
    if (d == 0 && lane == 0)   // publish trig table for bwd
        g_trig4[v] = make_float4(sv * DPf, cv * DPf, sv * INV_DPf, cv * INV_DPf);

    const float s128 = fmaf((float)d, DPf, OFFf);
    const float ax = fmaf(-s128, sv, 127.5f);   // xp = ax + t128*cv
    const float ay = fmaf( s128, cv, 127.5f);   // yp = ay + t128*sv

    float lo = -1e30f, hi = 1e30f;              // any-corner-valid superset
    float li = -1e30f, hii = 1e30f;             // all-corners-valid interior
    bool empty = false, iempty = false;
    slab(ax, cv, -1.001f, 256.001f, lo, hi, empty);
    slab(ay, sv, -1.001f, 256.001f, lo, hi, empty);
    slab(ax, cv, 0.001f, 254.999f, li, hii, iempty);
    slab(ay, sv, 0.001f, 254.999f, li, hii, iempty);

    float sA = 0.f, sB = 0.f;
    if (!empty && lo <= hi) {
        int kLo = max(0,     (int)ceilf ((lo - OFFf) * INV_DPf - 0.001f));
        int kHi = min(S - 1, (int)floorf((hi - OFFf) * INV_DPf + 0.001f));
        int kiLo, kiHi;
        if (iempty || li > hii) { kiLo = kHi + 1; kiHi = kHi; }
        else {
            kiLo = max(kLo, (int)ceilf ((li  - OFFf) * INV_DPf + 0.001f));
            kiHi = min(kHi, (int)floorf((hii - OFFf) * INV_DPf - 0.001f));
            if (kiLo > kiHi) { kiLo = kHi + 1; kiHi = kHi; }
        }

        // boundary prologue
        for (int k = kLo + lane; k < kiLo; k += 32) {
            float t128 = fmaf((float)k, DPf, OFFf);
            float xp = fmaf(t128, cv, ax), yp = fmaf(t128, sv, ay);
            float x0f = floorf(xp), y0f = floorf(yp);
            int ix0 = (int)x0f, iy0 = (int)y0f;
            int base = iy0 * W + ix0;
            float2 z = make_float2(0.f, 0.f);
            float2 p00 = z, p10 = z, p01 = z, p11 = z;
            bool vx0 = (unsigned)ix0       < (unsigned)W;
            bool vx1 = (unsigned)(ix0 + 1) < (unsigned)W;
            bool vy0 = (unsigned)iy0       < (unsigned)H;
            bool vy1 = (unsigned)(iy0 + 1) < (unsigned)H;
            if (vx0 && vy0) p00 = g_img2[base];
            if (vx1 && vy0) p10 = g_img2[base + 1];
            if (vx0 && vy1) p01 = g_img2[base + W];
            if (vx1 && vy1) p11 = g_img2[base + W + 1];
            accum4(p00, p10, p01, p11, xp - x0f, yp - y0f, sA, sB);
        }
        // interior: zero checks
        for (int k = kiLo + lane; k <= kiHi; k += 32) {
            float t128 = fmaf((float)k, DPf, OFFf);
            float xp = fmaf(t128, cv, ax), yp = fmaf(t128, sv, ay);
            float x0f = floorf(xp), y0f = floorf(yp);
            int base = (int)y0f * W + (int)x0f;
            float2 p00 = g_img2[base],     p10 = g_img2[base + 1];
            float2 p01 = g_img2[base + W], p11 = g_img2[base + W + 1];
            accum4(p00, p10, p01, p11, xp - x0f, yp - y0f, sA, sB);
        }
        // boundary epilogue
        for (int k = max(kiHi + 1, kLo) + lane; k <= kHi; k += 32) {
            float t128 = fmaf((float)k, DPf, OFFf);
            float xp = fmaf(t128, cv, ax), yp = fmaf(t128, sv, ay);
            float x0f = floorf(xp), y0f = floorf(yp);
            int ix0 = (int)x0f, iy0 = (int)y0f;
            int base = iy0 * W + ix0;
            float2 z = make_float2(0.f, 0.f);
            float2 p00 = z, p10 = z, p01 = z, p11 = z;
            bool vx0 = (unsigned)ix0       < (unsigned)W;
            bool vx1 = (unsigned)(ix0 + 1) < (unsigned)W;
            bool vy0 = (unsigned)iy0       < (unsigned)H;
            bool vy1 = (unsigned)(iy0 + 1) < (unsigned)H;
            if (vx0 && vy0) p00 = g_img2[base];
            if (vx1 && vy0) p10 = g_img2[base + 1];
            if (vx0 && vy1) p01 = g_img2[base + W];
            if (vx1 && vy1) p11 = g_img2[base + W + 1];
            accum4(p00, p10, p01, p11, xp - x0f, yp - y0f, sA, sB);
        }
    }
    #pragma unroll
    for (int o = 16; o; o >>= 1) {
        sA += __shfl_xor_sync(0xffffffffu, sA, o);
        sB += __shfl_xor_sync(0xffffffffu, sB, o);
    }
    if (lane == 0) {
        g_temp[warp] = make_float2(fmaf(DTf, sA, -__ldg(proj + warp)),
                                   fmaf(DTf, sB, -__ldg(proj + V * D + warp)));
    }
}

// ---------------------------------------------------------------------------
// backprojection (exact adjoint, gather) fused with the update.
// 128-thread blocks -> 512 blocks for wave balance (3.46 waves on 148 SMs).
// ---------------------------------------------------------------------------
__global__ void __launch_bounds__(128) bwd_kernel(const float* __restrict__ wptr,
                                                  float* __restrict__ out) {
    __shared__ float4 sg[V];
    const int tid = threadIdx.x;
    #pragma unroll
    for (int i = tid; i < V; i += 128) sg[i] = g_trig4[i];
    __syncthreads();

    const int p = blockIdx.x * 128 + tid;
    const int ix = p & (W - 1);
    const int iy = p >> 8;
    const float px = (float)ix - 127.5f;
    const float py = (float)iy - 127.5f;
    const float npx = -px;

    float accA = 0.f, accB = 0.f;
    const float2* __restrict__ row = g_temp;

    #pragma unroll 2
    for (int v = 0; v < V; ++v, row += D) {
        const float4 q = sg[v];
        const float svDP = q.x, cvDP = q.y, svI = q.z, cvI = q.w;

        const float jc = fmaf(py, cvI, fmaf(npx, svI, 127.5f));
        const float kc = fmaf(px, cvI, fmaf(py,  svI, 127.5f));
        const float jf = floorf(jc), kf = floorf(kc);
        const float fj = jc - jf,    fk = kc - kf;
        const int   j0 = (int)jf;

        const float dx00 = fmaf(fj, svDP, -(fk * cvDP));
        const float u    = fmaf(fj, cvDP,  (fk * svDP));
        const float dx10 = dx00 - svDP;
        const float dx01 = dx00 + cvDP;
        const float dx11 = dx10 + cvDP;
        const float e10  = u - cvDP;
        const float e01  = u - svDP;
        const float e11  = e10 - svDP;

        const float hx00 = __saturatef(1.f - fabsf(dx00));
        const float hx10 = __saturatef(1.f - fabsf(dx10));
        const float hx01 = __saturatef(1.f - fabsf(dx01));
        const float hx11 = __saturatef(1.f - fabsf(dx11));
        const float hy00 = __saturatef(1.f - fabsf(u));
        const float hy10 = __saturatef(1.f - fabsf(e10));
        const float hy01 = __saturatef(1.f - fabsf(e01));
        const float hy11 = __saturatef(1.f - fabsf(e11));

        const float q0 = fmaf(hx01, hy01, hx00 * hy00);
        const float q1 = fmaf(hx11, hy11, hx10 * hy10);

        const float2 t0 = __ldg(row + j0);
        const float2 t1 = __ldg(row + j0 + 1);
        accA = fmaf(t0.x, q0, fmaf(t1.x, q1, accA));
        accB = fmaf(t0.y, q0, fmaf(t1.y, q1, accB));
    }

    const float wdt = __ldg(wptr) * DTf;
    const float2 ipx = g_img2[p];
    out[p]      = fmaf(-wdt, accA, ipx.x);
    out[p + HW] = fmaf(-wdt, accB, ipx.y);
}

// ---------------------------------------------------------------------------
extern "C" void kernel_launch(void* const* d_in, const int* in_sizes, int n_in,
                              void* d_out, int out_size) {
    const float* img  = (const float*)d_in[0];   // [2,1,256,256]
    const float* proj = (const float*)d_in[1];   // [2,1,192,256]
    const float* wptr = (const float*)d_in[2];   // [1]
    float* out = (float*)d_out;                  // [2,1,256,256]

    prep_kernel<<<HW / 512, 256>>>(img);
    fwd_kernel<<<(V * D * 32) / 256, 256>>>(proj);
    bwd_kernel<<<HW / 128, 128>>>(wptr, out);
}

// round 4
// speedup vs baseline: 1.4843x; 1.1170x over previous
#include <cuda_runtime.h>
#include <math.h>

#define H 256
#define W 256
#define V 192
#define D 256
#define S 256
#define HW (H*W)

#define SQRT2_D 1.4142135623730951
#define DPf     ((float)(2.0 * SQRT2_D * 128.0 / 255.0))   /* sample spacing, 128-scaled px */
#define OFFf    ((float)(-SQRT2_D * 128.0))
#define INV_DPf ((float)(255.0 / (256.0 * SQRT2_D)))
#define DTf     ((float)(2.0 * SQRT2_D / 256.0))
#define PI_D    3.141592653589793

__device__ float2 g_img2[HW];      // (imgA, imgB) interleaved, row-major
__device__ float2 g_img2T[HW];     // same, transposed: [x*256 + y]
__device__ float2 g_temp[V * D];   // residual sinogram, (A,B) interleaved
__device__ float4 g_trig4[V];      // {svDP, cvDP, svI, cvI}, written by fwd

// ---------------------------------------------------------------------------
// prep: interleave the two images AND build a transposed copy (tiled via smem,
// all global accesses coalesced).
// ---------------------------------------------------------------------------
__global__ void __launch_bounds__(256) prep_kernel(const float* __restrict__ img) {
    __shared__ float2 tile[32][33];
    const int tx = threadIdx.x & 31;
    const int ty = threadIdx.x >> 5;            // 0..7
    const int bx = (blockIdx.x & 7) << 5;
    const int by = (blockIdx.x >> 3) << 5;
    #pragma unroll
    for (int r = 0; r < 32; r += 8) {
        int x = bx + tx, y = by + ty + r;
        int p = y * W + x;
        float2 val = make_float2(img[p], img[p + HW]);
        g_img2[p] = val;
        tile[ty + r][tx] = val;
    }
    __syncthreads();
    #pragma unroll
    for (int r = 0; r < 32; r += 8) {
        int xo = bx + ty + r, yo = by + tx;     // contiguous in yo=tx
        g_img2T[xo * H + yo] = tile[tx][ty + r];
    }
}

__device__ __forceinline__ void slab(float A, float dir, float b0, float b1,
                                     float& lo, float& hi, bool& empty) {
    if (fabsf(dir) > 1e-7f) {
        float r = 1.0f / dir;
        float t1 = (b0 - A) * r, t2 = (b1 - A) * r;
        lo = fmaxf(lo, fminf(t1, t2));
        hi = fminf(hi, fmaxf(t1, t2));
    } else if (A < b0 || A > b1) {
        empty = true;
    }
}

__device__ __forceinline__ void accum4(float2 p00, float2 p10, float2 p01, float2 p11,
                                       float fx, float fy, float& sA, float& sB) {
    float gx = 1.f - fx, gy = 1.f - fy;
    float w00 = gx * gy, w10 = fx * gy, w01 = gx * fy, w11 = fx * fy;
    sA = fmaf(p00.x, w00, fmaf(p10.x, w10, fmaf(p01.x, w01, fmaf(p11.x, w11, sA))));
    sB = fmaf(p00.y, w00, fmaf(p10.y, w10, fmaf(p01.y, w01, fmaf(p11.y, w11, sB))));
}

// ---------------------------------------------------------------------------
// forward projection: one warp per (v,d) ray, lanes stride over samples.
// Steep angles (|sv|>|cv|) read the TRANSPOSED image with x/y roles swapped so
// the fast-varying coordinate is always memory-contiguous (bilinear is exactly
// transpose-symmetric -> bitwise identical results, far fewer L1 sectors).
// 3-loop split: boundary | interior (no checks) | boundary. Warp-uniform bounds.
// ---------------------------------------------------------------------------
__global__ void __launch_bounds__(256) fwd_kernel(const float* __restrict__ proj) {
    const int warp = (blockIdx.x * blockDim.x + threadIdx.x) >> 5;
    const int lane = threadIdx.x & 31;
    const int v = warp >> 8;
    const int d = warp & 255;

    float cv, sv;
    {
        float af = (float)((double)v * (PI_D / 192.0));
        sincosf(af, &sv, &cv);
    }
    if (d == 0 && lane == 0)   // publish trig table for bwd
        g_trig4[v] = make_float4(sv * DPf, cv * DPf, sv * INV_DPf, cv * INV_DPf);

    const float s128 = fmaf((float)d, DPf, OFFf);
    const float ax0 = fmaf(-s128, sv, 127.5f);   // xp = ax0 + t128*cv
    const float ay0 = fmaf( s128, cv, 127.5f);   // yp = ay0 + t128*sv

    const bool steep = fabsf(sv) > fabsf(cv);    // warp-uniform
    const float2* __restrict__ im = steep ? g_img2T : g_img2;
    const float c2 = steep ? sv : cv;            // fast-coord direction
    const float s2 = steep ? cv : sv;            // slow-coord direction
    const float ax = steep ? ay0 : ax0;
    const float ay = steep ? ax0 : ay0;

    float lo = -1e30f, hi = 1e30f;               // any-corner-valid superset
    float li = -1e30f, hii = 1e30f;              // all-corners-valid interior
    bool empty = false, iempty = false;
    slab(ax, c2, -1.001f, 256.001f, lo, hi, empty);
    slab(ay, s2, -1.001f, 256.001f, lo, hi, empty);
    slab(ax, c2, 0.001f, 254.999f, li, hii, iempty);
    slab(ay, s2, 0.001f, 254.999f, li, hii, iempty);

    float sA = 0.f, sB = 0.f;
    if (!empty && lo <= hi) {
        int kLo = max(0,     (int)ceilf ((lo - OFFf) * INV_DPf - 0.001f));
        int kHi = min(S - 1, (int)floorf((hi - OFFf) * INV_DPf + 0.001f));
        int kiLo, kiHi;
        if (iempty || li > hii) { kiLo = kHi + 1; kiHi = kHi; }
        else {
            kiLo = max(kLo, (int)ceilf ((li  - OFFf) * INV_DPf + 0.001f));
            kiHi = min(kHi, (int)floorf((hii - OFFf) * INV_DPf - 0.001f));
            if (kiLo > kiHi) { kiLo = kHi + 1; kiHi = kHi; }
        }

        // boundary prologue
        for (int k = kLo + lane; k < kiLo; k += 32) {
            float t128 = fmaf((float)k, DPf, OFFf);
            float xp = fmaf(t128, c2, ax), yp = fmaf(t128, s2, ay);
            float x0f = floorf(xp), y0f = floorf(yp);
            int ix0 = (int)x0f, iy0 = (int)y0f;
            int base = iy0 * W + ix0;
            float2 z = make_float2(0.f, 0.f);
            float2 p00 = z, p10 = z, p01 = z, p11 = z;
            bool vx0 = (unsigned)ix0       < (unsigned)W;
            bool vx1 = (unsigned)(ix0 + 1) < (unsigned)W;
            bool vy0 = (unsigned)iy0       < (unsigned)H;
            bool vy1 = (unsigned)(iy0 + 1) < (unsigned)H;
            if (vx0 && vy0) p00 = im[base];
            if (vx1 && vy0) p10 = im[base + 1];
            if (vx0 && vy1) p01 = im[base + W];
            if (vx1 && vy1) p11 = im[base + W + 1];
            accum4(p00, p10, p01, p11, xp - x0f, yp - y0f, sA, sB);
        }
        // interior: zero checks
        for (int k = kiLo + lane; k <= kiHi; k += 32) {
            float t128 = fmaf((float)k, DPf, OFFf);
            float xp = fmaf(t128, c2, ax), yp = fmaf(t128, s2, ay);
            float x0f = floorf(xp), y0f = floorf(yp);
            int base = (int)y0f * W + (int)x0f;
            float2 p00 = im[base],     p10 = im[base + 1];
            float2 p01 = im[base + W], p11 = im[base + W + 1];
            accum4(p00, p10, p01, p11, xp - x0f, yp - y0f, sA, sB);
        }
        // boundary epilogue
        for (int k = max(kiHi + 1, kLo) + lane; k <= kHi; k += 32) {
            float t128 = fmaf((float)k, DPf, OFFf);
            float xp = fmaf(t128, c2, ax), yp = fmaf(t128, s2, ay);
            float x0f = floorf(xp), y0f = floorf(yp);
            int ix0 = (int)x0f, iy0 = (int)y0f;
            int base = iy0 * W + ix0;
            float2 z = make_float2(0.f, 0.f);
            float2 p00 = z, p10 = z, p01 = z, p11 = z;
            bool vx0 = (unsigned)ix0       < (unsigned)W;
            bool vx1 = (unsigned)(ix0 + 1) < (unsigned)W;
            bool vy0 = (unsigned)iy0       < (unsigned)H;
            bool vy1 = (unsigned)(iy0 + 1) < (unsigned)H;
            if (vx0 && vy0) p00 = im[base];
            if (vx1 && vy0) p10 = im[base + 1];
            if (vx0 && vy1) p01 = im[base + W];
            if (vx1 && vy1) p11 = im[base + W + 1];
            accum4(p00, p10, p01, p11, xp - x0f, yp - y0f, sA, sB);
        }
    }
    #pragma unroll
    for (int o = 16; o; o >>= 1) {
        sA += __shfl_xor_sync(0xffffffffu, sA, o);
        sB += __shfl_xor_sync(0xffffffffu, sB, o);
    }
    if (lane == 0) {
        g_temp[warp] = make_float2(fmaf(DTf, sA, -__ldg(proj + warp)),
                                   fmaf(DTf, sB, -__ldg(proj + V * D + warp)));
    }
}

// ---------------------------------------------------------------------------
// backprojection (exact adjoint, gather) fused with the update.
// 128-thread blocks -> 512 blocks for wave balance.
// ---------------------------------------------------------------------------
__global__ void __launch_bounds__(128) bwd_kernel(const float* __restrict__ wptr,
                                                  float* __restrict__ out) {
    __shared__ float4 sg[V];
    const int tid = threadIdx.x;
    #pragma unroll
    for (int i = tid; i < V; i += 128) sg[i] = g_trig4[i];
    __syncthreads();

    const int p = blockIdx.x * 128 + tid;
    const int ix = p & (W - 1);
    const int iy = p >> 8;
    const float px = (float)ix - 127.5f;
    const float py = (float)iy - 127.5f;
    const float npx = -px;

    float accA = 0.f, accB = 0.f;
    const float2* __restrict__ row = g_temp;

    #pragma unroll 2
    for (int v = 0; v < V; ++v, row += D) {
        const float4 q = sg[v];
        const float svDP = q.x, cvDP = q.y, svI = q.z, cvI = q.w;

        const float jc = fmaf(py, cvI, fmaf(npx, svI, 127.5f));
        const float kc = fmaf(px, cvI, fmaf(py,  svI, 127.5f));
        const float jf = floorf(jc), kf = floorf(kc);
        const float fj = jc - jf,    fk = kc - kf;
        const int   j0 = (int)jf;

        const float dx00 = fmaf(fj, svDP, -(fk * cvDP));
        const float u    = fmaf(fj, cvDP,  (fk * svDP));
        const float dx10 = dx00 - svDP;
        const float dx01 = dx00 + cvDP;
        const float dx11 = dx10 + cvDP;
        const float e10  = u - cvDP;
        const float e01  = u - svDP;
        const float e11  = e10 - svDP;

        const float hx00 = __saturatef(1.f - fabsf(dx00));
        const float hx10 = __saturatef(1.f - fabsf(dx10));
        const float hx01 = __saturatef(1.f - fabsf(dx01));
        const float hx11 = __saturatef(1.f - fabsf(dx11));
        const float hy00 = __saturatef(1.f - fabsf(u));
        const float hy10 = __saturatef(1.f - fabsf(e10));
        const float hy01 = __saturatef(1.f - fabsf(e01));
        const float hy11 = __saturatef(1.f - fabsf(e11));

        const float q0 = fmaf(hx01, hy01, hx00 * hy00);
        const float q1 = fmaf(hx11, hy11, hx10 * hy10);

        const float2 t0 = __ldg(row + j0);
        const float2 t1 = __ldg(row + j0 + 1);
        accA = fmaf(t0.x, q0, fmaf(t1.x, q1, accA));
        accB = fmaf(t0.y, q0, fmaf(t1.y, q1, accB));
    }

    const float wdt = __ldg(wptr) * DTf;
    const float2 ipx = g_img2[p];
    out[p]      = fmaf(-wdt, accA, ipx.x);
    out[p + HW] = fmaf(-wdt, accB, ipx.y);
}

// ---------------------------------------------------------------------------
extern "C" void kernel_launch(void* const* d_in, const int* in_sizes, int n_in,
                              void* d_out, int out_size) {
    const float* img  = (const float*)d_in[0];   // [2,1,256,256]
    const float* proj = (const float*)d_in[1];   // [2,1,192,256]
    const float* wptr = (const float*)d_in[2];   // [1]
    float* out = (float*)d_out;                  // [2,1,256,256]

    prep_kernel<<<64, 256>>>(img);
    fwd_kernel<<<(V * D * 32) / 256, 256>>>(proj);
    bwd_kernel<<<HW / 128, 128>>>(wptr, out);
}